// round 3
// baseline (speedup 1.0000x reference)
#include <cuda_runtime.h>

// GeodesicPathIntegrator: det(S) is EXACTLY real (S11=conj(S00), S10=-conj(S01)
// for quaternion-form SU(2) matrices), so angle(det) is pure fp32 FMA-contraction
// noise: Im(det) = +/-err(p*q) +/- err(r*s), where (p,q)=S00, (r,s)=S01 and
// err(x*y) = rn(xy) - xy (the exact product rounding error, representable in fp32).
// The outputs are means over 16.7M samples of this noise; matching the noise
// DISTRIBUTION gives agreement to ~1/sqrt(16.7M) ~ 2.4e-4 < 1e-3.  (Verified
// R2: rel_err = 2.57e-4.)  DO NOT change the contraction pattern below.
//
// R3: fuse the reduction into the main kernel (threadfence + ticket, last block
// reduces partials in fixed order -> value-deterministic), unroll 8 for MLP.

#define T_STEPS   33
#define N_STEPS   32
#define BK        (8192 * 64)          // 524288 (b,k) columns
#define THREADS_1 256
#define BLOCKS_1  (BK / THREADS_1)     // 2048
#define INV_PI    0.3183098861837907f

__device__ float        g_partials[BLOCKS_1];
__device__ unsigned int g_ticket = 0;   // reset to 0 by the last block each call

struct C2 { float re, im; };

// Complex multiply with pinned FMA contraction (mimics XLA/LLVM fp-contract):
//   re = fma(xr, yr, -(xi*yi)),  im = fma(xr, yi, xi*yr)
__device__ __forceinline__ C2 cmul(float xr, float xi, float yr, float yi) {
    C2 z;
    z.re = __fmaf_rn(xr, yr, -__fmul_rn(xi, yi));
    z.im = __fmaf_rn(xr, yi,  __fmul_rn(xi, yr));
    return z;
}

__global__ __launch_bounds__(THREADS_1)
void geo_fused(const float4* __restrict__ q, float* __restrict__ out, int out_size) {
    const int bk = blockIdx.x * THREADS_1 + threadIdx.x;

    float acc = 0.0f;
    float4 prev = q[bk];  // t = 0

#pragma unroll 8
    for (int t = 1; t < T_STEPS; t++) {
        const float4 cur = q[(size_t)t * BK + bk];
        const float a1 = prev.x, b1 = prev.y, c1 = prev.z, d1 = prev.w;
        const float a2 = cur.x,  b2 = cur.y,  c2 = cur.z,  d2 = cur.w;
        prev = cur;

        // s = [[a+di, b+ci], [-b+ci, a-di]];  S = s_next * s_t^H
        C2 t1 = cmul(a2, d2, a1, -d1);
        C2 t2 = cmul(b2, c2, b1, -c1);
        const float p  = t1.re + t2.re;   // S00.re
        const float qq = t1.im + t2.im;   // S00.im
        C2 t3 = cmul(a2, d2, -b1, -c1);
        C2 t4 = cmul(b2, c2,  a1,  d1);
        const float r = t3.re + t4.re;    // S01.re
        const float s = t3.im + t4.im;    // S01.im

        // det = |S00|^2 + |S01|^2 + FMA rounding noise in Im:
        const float im1 = __fmaf_rn(p, -qq, __fmul_rn(qq, p));   // rn(pq)-pq
        const float im2 = __fmaf_rn(r,  s,  __fmul_rn(s, -r));   // rs-rn(rs)
        const float det_im = im1 - im2;
        const float re1 = __fmaf_rn(p, p, -__fmul_rn(qq, -qq));
        const float re2 = __fmaf_rn(r, -r, -__fmul_rn(s, s));
        const float det_re = re1 - re2;   // = p^2+q^2+r^2+s^2 > 0

        acc += fabsf(__fdividef(det_im, det_re)) * INV_PI;
    }

    // ---- deterministic block reduction ----
    __shared__ float s_warp[THREADS_1 / 32];
    __shared__ bool  s_last;
    __shared__ double s_dbl[THREADS_1];
    const int lane = threadIdx.x & 31;
    const int wid  = threadIdx.x >> 5;
#pragma unroll
    for (int off = 16; off > 0; off >>= 1)
        acc += __shfl_down_sync(0xFFFFFFFFu, acc, off);
    if (lane == 0) s_warp[wid] = acc;
    __syncthreads();
    if (threadIdx.x == 0) {
        float v = 0.0f;
#pragma unroll
        for (int w = 0; w < THREADS_1 / 32; w++) v += s_warp[w];
        g_partials[blockIdx.x] = v;
        __threadfence();
        unsigned int t = atomicAdd(&g_ticket, 1u);
        s_last = (t == BLOCKS_1 - 1);
    }
    __syncthreads();

    // ---- last block: fixed-order final reduction (value-deterministic) ----
    if (s_last) {
        double d = 0.0;
        for (int i = threadIdx.x; i < BLOCKS_1; i += THREADS_1)
            d += (double)g_partials[i];
        s_dbl[threadIdx.x] = d;
        __syncthreads();
        for (int off = THREADS_1 / 2; off > 0; off >>= 1) {
            if (threadIdx.x < off) s_dbl[threadIdx.x] += s_dbl[threadIdx.x + off];
            __syncthreads();
        }
        if (threadIdx.x == 0) {
            const double total = s_dbl[0] / (double)BK;  // sum_t mean_{b,k}|eta|
            if (out_size > 0) out[0] = (float)(total / (double)N_STEPS); // avg_curvature
            if (out_size > 1) out[1] = (float)total;                     // total_eta
            g_ticket = 0;  // reset for next graph replay
        }
        // zero-fill any extra outputs (d_out is poisoned to 0xAA)
        for (int i = 2 + threadIdx.x; i < out_size; i += THREADS_1) out[i] = 0.0f;
    }
}

extern "C" void kernel_launch(void* const* d_in, const int* in_sizes, int n_in,
                              void* d_out, int out_size) {
    (void)in_sizes; (void)n_in;
    const float4* q = (const float4*)d_in[0];
    float* out = (float*)d_out;
    geo_fused<<<BLOCKS_1, THREADS_1>>>(q, out, out_size);
}

// round 4
// speedup vs baseline: 1.0243x; 1.0243x over previous
#include <cuda_runtime.h>

// GeodesicPathIntegrator: det(S) is EXACTLY real (S11=conj(S00), S10=-conj(S01)
// for quaternion-form SU(2) matrices), so angle(det) is pure fp32 FMA-contraction
// noise: Im(det) = +/-err(p*q) +/- err(r*s). Outputs are means over 16.7M
// samples; matching the noise DISTRIBUTION gives ~2.6e-4 rel_err (verified R2/R3).
// DO NOT change the contraction pattern in the t-loop.
//
// R4: unroll 4 (R2's measured-6.2TB/s schedule; unroll 8 serialized loads and
// cost 8us in R3) + fused ticket reduction (saves the 8.9us stage2 launch).

#define T_STEPS   33
#define N_STEPS   32
#define BK        (8192 * 64)          // 524288 (b,k) columns
#define THREADS_1 256
#define BLOCKS_1  (BK / THREADS_1)     // 2048
#define INV_PI    0.3183098861837907f

__device__ float        g_partials[BLOCKS_1];
__device__ unsigned int g_ticket = 0;   // reset by last block each call

struct C2 { float re, im; };

// Complex multiply with pinned FMA contraction (mimics XLA/LLVM fp-contract):
//   re = fma(xr, yr, -(xi*yi)),  im = fma(xr, yi, xi*yr)
__device__ __forceinline__ C2 cmul(float xr, float xi, float yr, float yi) {
    C2 z;
    z.re = __fmaf_rn(xr, yr, -__fmul_rn(xi, yi));
    z.im = __fmaf_rn(xr, yi,  __fmul_rn(xi, yr));
    return z;
}

__global__ __launch_bounds__(THREADS_1)
void geo_fused(const float4* __restrict__ q, float* __restrict__ out, int out_size) {
    const int bk = blockIdx.x * THREADS_1 + threadIdx.x;

    float acc = 0.0f;
    float4 prev = q[bk];  // t = 0

#pragma unroll 4
    for (int t = 1; t < T_STEPS; t++) {
        const float4 cur = q[(size_t)t * BK + bk];
        const float a1 = prev.x, b1 = prev.y, c1 = prev.z, d1 = prev.w;
        const float a2 = cur.x,  b2 = cur.y,  c2 = cur.z,  d2 = cur.w;
        prev = cur;

        // s = [[a+di, b+ci], [-b+ci, a-di]];  S = s_next * s_t^H
        C2 t1 = cmul(a2, d2, a1, -d1);
        C2 t2 = cmul(b2, c2, b1, -c1);
        const float p  = t1.re + t2.re;   // S00.re
        const float qq = t1.im + t2.im;   // S00.im
        C2 t3 = cmul(a2, d2, -b1, -c1);
        C2 t4 = cmul(b2, c2,  a1,  d1);
        const float r = t3.re + t4.re;    // S01.re
        const float s = t3.im + t4.im;    // S01.im

        // det = |S00|^2 + |S01|^2 + FMA rounding noise in Im:
        const float im1 = __fmaf_rn(p, -qq, __fmul_rn(qq, p));   // rn(pq)-pq
        const float im2 = __fmaf_rn(r,  s,  __fmul_rn(s, -r));   // rs-rn(rs)
        const float det_im = im1 - im2;
        const float re1 = __fmaf_rn(p, p, -__fmul_rn(qq, -qq));
        const float re2 = __fmaf_rn(r, -r, -__fmul_rn(s, s));
        const float det_re = re1 - re2;   // = p^2+q^2+r^2+s^2 > 0

        acc += fabsf(__fdividef(det_im, det_re)) * INV_PI;
    }

    // ---- deterministic block reduction ----
    __shared__ float  s_warp[THREADS_1 / 32];
    __shared__ bool   s_last;
    __shared__ double s_dbl[THREADS_1];
    const int lane = threadIdx.x & 31;
    const int wid  = threadIdx.x >> 5;
#pragma unroll
    for (int off = 16; off > 0; off >>= 1)
        acc += __shfl_down_sync(0xFFFFFFFFu, acc, off);
    if (lane == 0) s_warp[wid] = acc;
    __syncthreads();
    if (threadIdx.x == 0) {
        float v = 0.0f;
#pragma unroll
        for (int w = 0; w < THREADS_1 / 32; w++) v += s_warp[w];
        g_partials[blockIdx.x] = v;
        __threadfence();
        unsigned int t = atomicAdd(&g_ticket, 1u);
        s_last = (t == BLOCKS_1 - 1);
    }
    __syncthreads();

    // ---- last block: fixed-order final reduction (value-deterministic) ----
    if (s_last) {
        const float4* p4 = (const float4*)g_partials;  // 512 float4s
        double d = 0.0;
        for (int i = threadIdx.x; i < BLOCKS_1 / 4; i += THREADS_1) {
            const float4 v = p4[i];
            d += (double)v.x + (double)v.y + (double)v.z + (double)v.w;
        }
        s_dbl[threadIdx.x] = d;
        __syncthreads();
        for (int off = THREADS_1 / 2; off > 0; off >>= 1) {
            if (threadIdx.x < off) s_dbl[threadIdx.x] += s_dbl[threadIdx.x + off];
            __syncthreads();
        }
        if (threadIdx.x == 0) {
            const double total = s_dbl[0] / (double)BK;  // sum_t mean|eta|
            if (out_size > 0) out[0] = (float)(total / (double)N_STEPS); // avg
            if (out_size > 1) out[1] = (float)total;                     // total
            g_ticket = 0;  // reset for next graph replay
        }
        for (int i = 2 + threadIdx.x; i < out_size; i += THREADS_1) out[i] = 0.0f;
    }
}

extern "C" void kernel_launch(void* const* d_in, const int* in_sizes, int n_in,
                              void* d_out, int out_size) {
    (void)in_sizes; (void)n_in;
    const float4* q = (const float4*)d_in[0];
    float* out = (float*)d_out;
    geo_fused<<<BLOCKS_1, THREADS_1>>>(q, out, out_size);
}

// round 5
// speedup vs baseline: 1.1397x; 1.1127x over previous
#include <cuda_runtime.h>

// GeodesicPathIntegrator: det(S) is EXACTLY real (S11=conj(S00), S10=-conj(S01)
// for quaternion-form SU(2) matrices), so angle(det) is pure fp32 FMA-contraction
// noise: Im(det) = +/-err(p*q) +/- err(r*s). Outputs are means over 16.7M
// samples; matching the noise DISTRIBUTION gives ~2.6e-4 rel_err (verified
// R2-R4). DO NOT change the per-element contraction pattern.
//
// R5: two independent columns per thread (doubles MLP + ILP; R3/R4 showed
// ptxas won't front-batch loads within one chain). Fused ticket reduction kept.

#define T_STEPS   33
#define N_STEPS   32
#define BK        (8192 * 64)          // 524288 (b,k) columns
#define THREADS_1 256
#define COLS_PER_THREAD 2
#define BLOCKS_1  (BK / (THREADS_1 * COLS_PER_THREAD))   // 1024
#define INV_PI    0.3183098861837907f

__device__ float        g_partials[BLOCKS_1];
__device__ unsigned int g_ticket = 0;   // reset by last block each call

struct C2 { float re, im; };

// Complex multiply with pinned FMA contraction (mimics XLA/LLVM fp-contract):
__device__ __forceinline__ C2 cmul(float xr, float xi, float yr, float yi) {
    C2 z;
    z.re = __fmaf_rn(xr, yr, -__fmul_rn(xi, yi));
    z.im = __fmaf_rn(xr, yi,  __fmul_rn(xi, yr));
    return z;
}

// One (prev,cur) step of the frozen eta computation.
__device__ __forceinline__ float eta_step(const float4 prev, const float4 cur) {
    const float a1 = prev.x, b1 = prev.y, c1 = prev.z, d1 = prev.w;
    const float a2 = cur.x,  b2 = cur.y,  c2 = cur.z,  d2 = cur.w;

    C2 t1 = cmul(a2, d2, a1, -d1);
    C2 t2 = cmul(b2, c2, b1, -c1);
    const float p  = t1.re + t2.re;   // S00.re
    const float qq = t1.im + t2.im;   // S00.im
    C2 t3 = cmul(a2, d2, -b1, -c1);
    C2 t4 = cmul(b2, c2,  a1,  d1);
    const float r = t3.re + t4.re;    // S01.re
    const float s = t3.im + t4.im;    // S01.im

    const float im1 = __fmaf_rn(p, -qq, __fmul_rn(qq, p));   // rn(pq)-pq
    const float im2 = __fmaf_rn(r,  s,  __fmul_rn(s, -r));   // rs-rn(rs)
    const float det_im = im1 - im2;
    const float re1 = __fmaf_rn(p, p, -__fmul_rn(qq, -qq));
    const float re2 = __fmaf_rn(r, -r, -__fmul_rn(s, s));
    const float det_re = re1 - re2;   // = p^2+q^2+r^2+s^2 > 0

    return fabsf(__fdividef(det_im, det_re)) * INV_PI;
}

__global__ __launch_bounds__(THREADS_1)
void geo_fused(const float4* __restrict__ q, float* __restrict__ out, int out_size) {
    const int base = blockIdx.x * (THREADS_1 * COLS_PER_THREAD) + threadIdx.x;
    const int bk0 = base;
    const int bk1 = base + THREADS_1;

    float acc0 = 0.0f, acc1 = 0.0f;
    float4 prev0 = q[bk0];
    float4 prev1 = q[bk1];

#pragma unroll 2
    for (int t = 1; t < T_STEPS; t++) {
        const float4 cur0 = q[(size_t)t * BK + bk0];
        const float4 cur1 = q[(size_t)t * BK + bk1];
        acc0 += eta_step(prev0, cur0);
        acc1 += eta_step(prev1, cur1);
        prev0 = cur0;
        prev1 = cur1;
    }
    float acc = acc0 + acc1;

    // ---- deterministic block reduction ----
    __shared__ float  s_warp[THREADS_1 / 32];
    __shared__ bool   s_last;
    __shared__ double s_dbl[THREADS_1];
    const int lane = threadIdx.x & 31;
    const int wid  = threadIdx.x >> 5;
#pragma unroll
    for (int off = 16; off > 0; off >>= 1)
        acc += __shfl_down_sync(0xFFFFFFFFu, acc, off);
    if (lane == 0) s_warp[wid] = acc;
    __syncthreads();
    if (threadIdx.x == 0) {
        float v = 0.0f;
#pragma unroll
        for (int w = 0; w < THREADS_1 / 32; w++) v += s_warp[w];
        g_partials[blockIdx.x] = v;
        __threadfence();
        unsigned int t = atomicAdd(&g_ticket, 1u);
        s_last = (t == BLOCKS_1 - 1);
    }
    __syncthreads();

    // ---- last block: fixed-order final reduction (value-deterministic) ----
    if (s_last) {
        const float4* p4 = (const float4*)g_partials;  // 256 float4s
        double d = 0.0;
        for (int i = threadIdx.x; i < BLOCKS_1 / 4; i += THREADS_1) {
            const float4 v = p4[i];
            d += (double)v.x + (double)v.y + (double)v.z + (double)v.w;
        }
        s_dbl[threadIdx.x] = d;
        __syncthreads();
        for (int off = THREADS_1 / 2; off > 0; off >>= 1) {
            if (threadIdx.x < off) s_dbl[threadIdx.x] += s_dbl[threadIdx.x + off];
            __syncthreads();
        }
        if (threadIdx.x == 0) {
            const double total = s_dbl[0] / (double)BK;  // sum_t mean|eta|
            if (out_size > 0) out[0] = (float)(total / (double)N_STEPS); // avg
            if (out_size > 1) out[1] = (float)total;                     // total
            g_ticket = 0;  // reset for next graph replay
        }
        for (int i = 2 + threadIdx.x; i < out_size; i += THREADS_1) out[i] = 0.0f;
    }
}

extern "C" void kernel_launch(void* const* d_in, const int* in_sizes, int n_in,
                              void* d_out, int out_size) {
    (void)in_sizes; (void)n_in;
    const float4* q = (const float4*)d_in[0];
    float* out = (float*)d_out;
    geo_fused<<<BLOCKS_1, THREADS_1>>>(q, out, out_size);
}